// round 12
// baseline (speedup 1.0000x reference)
#include <cuda_runtime.h>
#include <cuda_fp16.h>
#include <cstdint>

typedef unsigned int u32;

// ---------------- problem constants ----------------
#define Bn 8
#define Nn 40962
#define Dn 40
#define Hn 512
#define DDn 32
#define KTOT 160               // 4 neighbors * 40
#define M_TOT (Bn*Nn)          // 327696
#define TMm 32                 // rows per CTA (4 CTAs/SM)
#define NTH 128
#define NBLK ((M_TOT + TMm - 1)/TMm)   // 10241
#define KA16 10                // GEMM1 k-atoms of 16 (160/16)

// ---------------- smem layout (u32 indices) ----------------
// region A: max(Zf 2560 u32, red 3456 f32) = 3456
#define SM_Z    0
#define SM_B1   3456
#define SM_B2   (SM_B1 + 512)
#define SM_BAS  (SM_B2 + 32)
#define SM_U32S (SM_BAS + 128)         // 4128
#define SMEM_BYTES (SM_U32S*4)         // 16512

// ---------------- helpers ----------------
__device__ __forceinline__ u32 pack2(float a, float b) {
    __half2 h = __floats2half2_rn(a, b);
    return *(u32*)&h;
}
// paired gelu -> packed fp16x2, one MUFU per pair (tanh.approx.f16x2)
__device__ __forceinline__ u32 gelu2(float x0, float x1) {
    float u0 = x0 * (0.7978845608028654f + 0.0356774081f * x0 * x0);
    float u1 = x1 * (0.7978845608028654f + 0.0356774081f * x1 * x1);
    u32 uh = pack2(u0, u1);
    u32 th; asm("tanh.approx.f16x2 %0, %1;" : "=r"(th) : "r"(uh));
    __half2 t = *(__half2*)&th;
    __half2 xh = __floats2half2_rn(x0, x1);
    const __half2 c05 = __float2half2_rn(0.5f);
    __half2 h = __hmul2(xh, __hfma2(t, c05, c05));   // x * (0.5*t + 0.5)
    return *(u32*)&h;
}

// m16n8k16 fp16 HMMA: D(f32) += A(f16) * B(f16)
#define MMAH(D, A, b0, b1) \
    asm("mma.sync.aligned.m16n8k16.row.col.f32.f16.f16.f32 " \
        "{%0,%1,%2,%3}, {%4,%5,%6,%7}, {%8,%9}, {%0,%1,%2,%3};" \
        : "+f"((D)[0]), "+f"((D)[1]), "+f"((D)[2]), "+f"((D)[3]) \
        : "r"((A)[0]), "r"((A)[1]), "r"((A)[2]), "r"((A)[3]), "r"(b0), "r"(b1))

// ---------------- global scratch ----------------
// W1 fp16 B-fragments: [ka16(10)][npair(32)][lane(32)] x uint4
__device__ uint4 g_W1h[KA16 * 32 * 32];
// W2 fp16 B-fragments: [gka16(32)][pa(2)][lane(32)] x uint4
__device__ uint4 g_W2h[32 * 2 * 32];
__device__ float  g_xbuf[(size_t)M_TOT * Dn];        // fp32 state ping-pong
__device__ __half g_xh0[(size_t)M_TOT * Dn];         // fp16 state mirror (ping)
__device__ __half g_xh1[(size_t)M_TOT * Dn];         // fp16 state mirror (pong)

// prep: W1 -> fp16 B-frag order.
__global__ void prep_w1h(const float* __restrict__ W1) {
    int i = blockIdx.x * 256 + threadIdx.x;
    if (i >= KA16 * 32 * 32 * 4) return;
    int q    = i & 3;
    int lane = (i >> 2) & 31;
    int np   = (i >> 7) & 31;
    int ka   = i >> 12;
    int k = ka * 16 + (lane & 3) * 2 + (q & 1) * 8;
    int n = np * 16 + ((q >> 1) << 3) + (lane >> 2);
    float v0 = __ldg(&W1[(size_t)k * Hn + n]);
    float v1 = __ldg(&W1[(size_t)(k + 1) * Hn + n]);
    ((u32*)g_W1h)[i] = pack2(v0, v1);
}

// prep: W2 -> fp16 B-frag order (identity k mapping).
__global__ void prep_w2h(const float* __restrict__ W2) {
    int i = blockIdx.x * 256 + threadIdx.x;
    if (i >= 32 * 2 * 32 * 4) return;
    int q    = i & 3;
    int lane = (i >> 2) & 31;
    int pa   = (i >> 7) & 1;
    int gka  = i >> 8;
    int r = gka * 16 + (lane & 3) * 2 + (q & 1) * 8;
    int n = pa * 16 + ((q >> 1) << 3) + (lane >> 2);
    float v0 = __ldg(&W2[r * DDn + n]);
    float v1 = __ldg(&W2[(r + 1) * DDn + n]);
    ((u32*)g_W2h)[i] = pack2(v0, v1);
}

// prep: fp32 x -> fp16 mirror (8 elems per thread)
__global__ void prep_xh(const float* __restrict__ x) {
    int i = blockIdx.x * 256 + threadIdx.x;
    if (i >= (M_TOT * Dn) / 8) return;
    const float4* p = (const float4*)(x + (size_t)i * 8);
    float4 a = __ldg(p), b = __ldg(p + 1);
    uint4 o;
    o.x = pack2(a.x, a.y); o.y = pack2(a.z, a.w);
    o.z = pack2(b.x, b.y); o.w = pack2(b.z, b.w);
    ((uint4*)g_xh0)[i] = o;
}

// ---------------- fused Euler step ----------------
__global__ void __launch_bounds__(NTH, 4)
step_kernel(const float* __restrict__ src, float* __restrict__ dst,
            const __half* __restrict__ mh_src, __half* __restrict__ mh_dst,
            const int* __restrict__ index,
            const uint4* __restrict__ W1h, const uint4* __restrict__ W2h,
            const float* __restrict__ b1, const float* __restrict__ b2)
{
    extern __shared__ u32 smu[];
    u32*   Zu  = smu;                    // fp16 A-frags: [mb(2)][ka16(10)][lane(32)][slot(4)]
    float* b1s = (float*)(smu + SM_B1);
    float* b2s = (float*)(smu + SM_B2);
    int*   bas = (int*)(smu + SM_BAS);
    float* red = (float*)smu;            // reduction scratch reuses Zf after GEMMs

    const int tid  = threadIdx.x;
    const int lane = tid & 31;
    const int wn   = tid >> 5;   // warp = N slice: 32-col slice within each 128-chunk (0..3)
    const int m0   = blockIdx.x * TMm;
    const int rows_valid = min(TMm, M_TOT - m0);

    // gather bases (element offsets; one per thread: 32 rows x 4 neighbors)
    {
        int r = tid >> 2, k = tid & 3;
        int base = 0;
        if (r < rows_valid) {
            int m = m0 + r, b = m / Nn, n = m - b * Nn;
            base = (b * Nn + __ldg(&index[n * 4 + k])) * Dn;
        }
        bas[tid] = base;
    }
    ((float4*)b1s)[tid] = __ldg(((const float4*)b1) + tid);
    if (tid < 8) ((float4*)b2s)[tid] = __ldg(((const float4*)b2) + tid);
    __syncthreads();

    // ---- gather Z (fp16 mirror) -> fp16 A-fragment layout ----
    // 5 uint4 per thread (80B rows), it-major coalescing, no conversions:
    // each uint4 = 8 consecutive k halves of one row = 4 u32 frag words.
    {
        uint4 gv[5];
        int rka[5], ita[5];
        #pragma unroll
        for (int j = 0; j < 5; ++j) {
            int t  = j * NTH + tid;          // 0..639
            int rk = t / 5;
            int it = t - rk * 5;
            rka[j] = rk; ita[j] = it;
            gv[j] = __ldg((const uint4*)(mh_src + bas[rk]) + it);
        }
        #pragma unroll
        for (int j = 0; j < 5; ++j) {
            int rk = rka[j], it = ita[j];
            int r  = rk >> 2, kn = rk & 3;
            int K0 = kn * 40 + it * 8;
            int ka = K0 >> 4;
            int kkhi = (K0 >> 3) & 1;
            int mb = r >> 4, rr = r & 15;
            int slot = (rr >> 3) + (kkhi << 1);
            int base = ((mb * KA16 + ka) * 32 + ((rr & 7) << 2)) * 4 + slot;
            Zu[base]      = gv[j].x;
            Zu[base + 4]  = gv[j].y;
            Zu[base + 8]  = gv[j].z;
            Zu[base + 12] = gv[j].w;
        }
    }
    __syncthreads();

    float d2[2][4][4];
    #pragma unroll
    for (int m = 0; m < 2; ++m)
        #pragma unroll
        for (int a = 0; a < 4; ++a)
            #pragma unroll
            for (int q = 0; q < 4; ++q) d2[m][a][q] = 0.f;

    const uint4* Za = (const uint4*)Zu;
    const int np0  = wn * 2;     // warp's first npair within each 128-col chunk
    const int ccol = 2 * (lane & 3);

    // ---- 4 H-chunks of 128 cols; NOT unrolled (R9: full unroll spills) ----
    #pragma unroll 1
    for (int nc = 0; nc < 4; ++nc) {
        const int npA = nc * 8 + np0;     // warp's npair indices: npA, npA+1
        float d1[2][4][4];
        #pragma unroll
        for (int m = 0; m < 2; ++m)
            #pragma unroll
            for (int a = 0; a < 4; ++a)
                #pragma unroll
                for (int q = 0; q < 4; ++q) d1[m][a][q] = 0.f;

        // distance-2 register prefetch of W1 fp16 B-frags (L2/L1-resident)
        uint4 pfA[2], pfB[2];
        #pragma unroll
        for (int p = 0; p < 2; ++p) {
            pfA[p] = __ldg(W1h + (0 * 32 + npA + p) * 32 + lane);
            pfB[p] = __ldg(W1h + (1 * 32 + npA + p) * 32 + lane);
        }

        #pragma unroll
        for (int ka = 0; ka < KA16; ka += 2) {
            // ---- even k-atom (pfA) ----
            {
                uint4 av0 = Za[(0 * KA16 + ka) * 32 + lane];
                uint4 av1 = Za[(1 * KA16 + ka) * 32 + lane];
                u32 a0[4] = {av0.x, av0.y, av0.z, av0.w};
                u32 a1[4] = {av1.x, av1.y, av1.z, av1.w};
                MMAH(d1[0][0], a0, pfA[0].x, pfA[0].y);
                MMAH(d1[1][0], a1, pfA[0].x, pfA[0].y);
                MMAH(d1[0][1], a0, pfA[0].z, pfA[0].w);
                MMAH(d1[1][1], a1, pfA[0].z, pfA[0].w);
                MMAH(d1[0][2], a0, pfA[1].x, pfA[1].y);
                MMAH(d1[1][2], a1, pfA[1].x, pfA[1].y);
                MMAH(d1[0][3], a0, pfA[1].z, pfA[1].w);
                MMAH(d1[1][3], a1, pfA[1].z, pfA[1].w);
                if (ka + 2 < KA16) {
                    #pragma unroll
                    for (int p = 0; p < 2; ++p)
                        pfA[p] = __ldg(W1h + ((ka + 2) * 32 + npA + p) * 32 + lane);
                }
            }
            // ---- odd k-atom (pfB) ----
            {
                uint4 av0 = Za[(0 * KA16 + ka + 1) * 32 + lane];
                uint4 av1 = Za[(1 * KA16 + ka + 1) * 32 + lane];
                u32 a0[4] = {av0.x, av0.y, av0.z, av0.w};
                u32 a1[4] = {av1.x, av1.y, av1.z, av1.w};
                MMAH(d1[0][0], a0, pfB[0].x, pfB[0].y);
                MMAH(d1[1][0], a1, pfB[0].x, pfB[0].y);
                MMAH(d1[0][1], a0, pfB[0].z, pfB[0].w);
                MMAH(d1[1][1], a1, pfB[0].z, pfB[0].w);
                MMAH(d1[0][2], a0, pfB[1].x, pfB[1].y);
                MMAH(d1[1][2], a1, pfB[1].x, pfB[1].y);
                MMAH(d1[0][3], a0, pfB[1].z, pfB[1].w);
                MMAH(d1[1][3], a1, pfB[1].z, pfB[1].w);
                if (ka + 3 < KA16) {
                    #pragma unroll
                    for (int p = 0; p < 2; ++p)
                        pfB[p] = __ldg(W1h + ((ka + 3) * 32 + npA + p) * 32 + lane);
                }
            }
        }

        // ---- gelu (fp16x2 tanh) + GEMM2 partial, h fed straight from registers ----
        const int colbase = nc * 128 + wn * 32;
        #pragma unroll
        for (int pg = 0; pg < 2; ++pg) {
            int cE = colbase + (2 * pg) * 8 + ccol;       // even atom cols
            int cO = cE + 8;                              // odd atom cols
            float bEa = b1s[cE], bEb = b1s[cE + 1];
            float bOa = b1s[cO], bOb = b1s[cO + 1];
            u32 A2[2][4];
            #pragma unroll
            for (int m = 0; m < 2; ++m) {
                A2[m][0] = gelu2(d1[m][2*pg][0]   + bEa, d1[m][2*pg][1]   + bEb);
                A2[m][1] = gelu2(d1[m][2*pg][2]   + bEa, d1[m][2*pg][3]   + bEb);
                A2[m][2] = gelu2(d1[m][2*pg+1][0] + bOa, d1[m][2*pg+1][1] + bOb);
                A2[m][3] = gelu2(d1[m][2*pg+1][2] + bOa, d1[m][2*pg+1][3] + bOb);
            }
            int gka = nc * 8 + wn * 2 + pg;               // H 16-row block (0..31)
            #pragma unroll
            for (int pa = 0; pa < 2; ++pa) {
                uint4 w = __ldg(W2h + (gka * 2 + pa) * 32 + lane);
                MMAH(d2[0][2*pa],   A2[0], w.x, w.y);
                MMAH(d2[1][2*pa],   A2[1], w.x, w.y);
                MMAH(d2[0][2*pa+1], A2[0], w.z, w.w);
                MMAH(d2[1][2*pa+1], A2[1], w.z, w.w);
            }
        }
    }

    __syncthreads();   // all Zf reads done before red overwrites it

    // ---- cross-wn reduction: wn=1..3 store partial d2, wn=0 adds ----
    if (wn >= 1) {
        float* rp = red + ((wn - 1) * 32 + lane) * 36;
        #pragma unroll
        for (int m = 0; m < 2; ++m)
            #pragma unroll
            for (int a = 0; a < 4; ++a)
                *(float4*)&rp[(m * 4 + a) * 4] =
                    make_float4(d2[m][a][0], d2[m][a][1], d2[m][a][2], d2[m][a][3]);
    }
    __syncthreads();

    if (wn == 0) {
        #pragma unroll
        for (int s = 0; s < 3; ++s) {
            const float* rp = red + (s * 32 + lane) * 36;
            #pragma unroll
            for (int m = 0; m < 2; ++m)
                #pragma unroll
                for (int a = 0; a < 4; ++a) {
                    float4 v = *(const float4*)&rp[(m * 4 + a) * 4];
                    d2[m][a][0] += v.x; d2[m][a][1] += v.y;
                    d2[m][a][2] += v.z; d2[m][a][3] += v.w;
                }
        }
        // epilogue: dst = x + 0.1*(d2 + b2); also refresh fp16 mirror (dims 0..31)
        #pragma unroll
        for (int m = 0; m < 2; ++m)
            #pragma unroll
            for (int rr = 0; rr < 2; ++rr) {
                int row = m * 16 + rr * 8 + (lane >> 2);
                if (row < rows_valid) {
                    size_t rb = (size_t)(m0 + row) * Dn;
                    u32* mrow = (u32*)(mh_dst + rb);
                    #pragma unroll
                    for (int a = 0; a < 4; ++a) {
                        int c = a * 8 + ccol;
                        float2 xv = __ldg((const float2*)(src + rb + c));
                        float2 ov;
                        ov.x = xv.x + 0.1f * (d2[m][a][rr*2]     + b2s[c]);
                        ov.y = xv.y + 0.1f * (d2[m][a][rr*2 + 1] + b2s[c+1]);
                        *(float2*)(dst + rb + c) = ov;
                        mrow[c >> 1] = pack2(ov.x, ov.y);
                    }
                }
            }
    } else if (wn == 1) {
        // static dims 32..39 (unchanged by Euler step); copy fp32 + fp16 mirror
        int row = lane;
        if (row < rows_valid) {
            size_t rb = (size_t)(m0 + row) * Dn;
            float4 s0 = __ldg((const float4*)(src + rb + 32));
            float4 s1 = __ldg((const float4*)(src + rb + 36));
            *(float4*)(dst + rb + 32) = s0;
            *(float4*)(dst + rb + 36) = s1;
            uint4 mh = __ldg((const uint4*)(mh_src + rb + 32));
            *(uint4*)(mh_dst + rb + 32) = mh;
        }
    }
}

extern "C" void kernel_launch(void* const* d_in, const int* in_sizes, int n_in,
                              void* d_out, int out_size)
{
    const float* x     = (const float*)d_in[0];
    const int*   index = (const int*)  d_in[1];
    const float* W1    = (const float*)d_in[2];
    const float* b1    = (const float*)d_in[3];
    const float* W2    = (const float*)d_in[4];
    const float* b2    = (const float*)d_in[5];
    float* out = (float*)d_out;

    float* buf = nullptr;
    uint4 *w1h = nullptr, *w2h = nullptr;
    __half *mh0 = nullptr, *mh1 = nullptr;
    cudaGetSymbolAddress((void**)&buf, g_xbuf);
    cudaGetSymbolAddress((void**)&w1h, g_W1h);
    cudaGetSymbolAddress((void**)&w2h, g_W2h);
    cudaGetSymbolAddress((void**)&mh0, g_xh0);
    cudaGetSymbolAddress((void**)&mh1, g_xh1);

    cudaFuncSetAttribute(step_kernel, cudaFuncAttributeMaxDynamicSharedMemorySize, SMEM_BYTES);

    prep_w1h<<<(KA16*32*32*4 + 255)/256, 256>>>(W1);
    prep_w2h<<<(32*2*32*4 + 255)/256, 256>>>(W2);
    prep_xh<<<((M_TOT*Dn/8) + 255)/256, 256>>>(x);

    dim3 grid(NBLK), block(NTH);
    step_kernel<<<grid, block, SMEM_BYTES>>>(x,   buf, mh0, mh1, index, w1h, w2h, b1, b2);
    step_kernel<<<grid, block, SMEM_BYTES>>>(buf, out, mh1, mh0, index, w1h, w2h, b1, b2);
    step_kernel<<<grid, block, SMEM_BYTES>>>(out, buf, mh0, mh1, index, w1h, w2h, b1, b2);
    step_kernel<<<grid, block, SMEM_BYTES>>>(buf, out, mh1, mh0, index, w1h, w2h, b1, b2);
}

// round 13
// speedup vs baseline: 1.1898x; 1.1898x over previous
#include <cuda_runtime.h>
#include <cuda_fp16.h>
#include <cstdint>

typedef unsigned int u32;

// ---------------- problem constants ----------------
#define Bn 8
#define Nn 40962
#define Dn 40
#define Hn 512
#define DDn 32
#define KTOT 160               // 4 neighbors * 40
#define M_TOT (Bn*Nn)          // 327696
#define TMm 32                 // rows per CTA (4 CTAs/SM)
#define NTH 128
#define NBLK ((M_TOT + TMm - 1)/TMm)   // 10241
#define KA16 10                // GEMM1 k-atoms of 16 (160/16)

// ---------------- smem layout (u32 indices) ----------------
// region A: max(Zf 2560 u32, red 3456 f32) = 3456
#define SM_Z    0
#define SM_B1   3456           // b1 as half2: 256 u32 (slot is 512 wide, fine)
#define SM_B2   (SM_B1 + 512)
#define SM_BAS  (SM_B2 + 32)
#define SM_U32S (SM_BAS + 128)         // 4128
#define SMEM_BYTES (SM_U32S*4)         // 16512

// ---------------- helpers ----------------
__device__ __forceinline__ u32 pack2(float a, float b) {
    __half2 h = __floats2half2_rn(a, b);
    return *(u32*)&h;
}
// full-half2 gelu: u = x*(c1 + c2*x^2); h = x*(0.5*tanh(u)+0.5)
__device__ __forceinline__ u32 gelu2h(u32 xu) {
    __half2 xh = *(__half2*)&xu;
    const __half2 c1h = __float2half2_rn(0.7978845608028654f);
    const __half2 c2h = __float2half2_rn(0.0356774081f);
    const __half2 c05 = __float2half2_rn(0.5f);
    __half2 x2 = __hmul2(xh, xh);
    __half2 u  = __hmul2(xh, __hfma2(c2h, x2, c1h));
    u32 uu = *(u32*)&u;
    u32 tu; asm("tanh.approx.f16x2 %0, %1;" : "=r"(tu) : "r"(uu));
    __half2 t = *(__half2*)&tu;
    __half2 h = __hmul2(xh, __hfma2(t, c05, c05));
    return *(u32*)&h;
}

// m16n8k16 fp16 HMMA, f32 accum (GEMM2)
#define MMAH(D, A, b0, b1) \
    asm("mma.sync.aligned.m16n8k16.row.col.f32.f16.f16.f32 " \
        "{%0,%1,%2,%3}, {%4,%5,%6,%7}, {%8,%9}, {%0,%1,%2,%3};" \
        : "+f"((D)[0]), "+f"((D)[1]), "+f"((D)[2]), "+f"((D)[3]) \
        : "r"((A)[0]), "r"((A)[1]), "r"((A)[2]), "r"((A)[3]), "r"(b0), "r"(b1))
// m16n8k16 fp16 HMMA, f16 accum (GEMM1): D = 2 u32 (4 halves)
#define MMAH2(D, A, b0, b1) \
    asm("mma.sync.aligned.m16n8k16.row.col.f16.f16.f16.f16 " \
        "{%0,%1}, {%2,%3,%4,%5}, {%6,%7}, {%0,%1};" \
        : "+r"((D)[0]), "+r"((D)[1]) \
        : "r"((A)[0]), "r"((A)[1]), "r"((A)[2]), "r"((A)[3]), "r"(b0), "r"(b1))

// ---------------- global scratch ----------------
// W1 fp16 B-fragments: [ka16(10)][npair(32)][lane(32)] x uint4
__device__ uint4 g_W1h[KA16 * 32 * 32];
// W2 fp16 B-fragments: [gka16(32)][pa(2)][lane(32)] x uint4
__device__ uint4 g_W2h[32 * 2 * 32];
__device__ float g_xbuf[(size_t)M_TOT * Dn];

// prep: W1 -> fp16 B-frag order.
__global__ void prep_w1h(const float* __restrict__ W1) {
    int i = blockIdx.x * 256 + threadIdx.x;
    if (i >= KA16 * 32 * 32 * 4) return;
    int q    = i & 3;
    int lane = (i >> 2) & 31;
    int np   = (i >> 7) & 31;
    int ka   = i >> 12;
    int k = ka * 16 + (lane & 3) * 2 + (q & 1) * 8;
    int n = np * 16 + ((q >> 1) << 3) + (lane >> 2);
    float v0 = __ldg(&W1[(size_t)k * Hn + n]);
    float v1 = __ldg(&W1[(size_t)(k + 1) * Hn + n]);
    ((u32*)g_W1h)[i] = pack2(v0, v1);
}

// prep: W2 -> fp16 B-frag order (identity k mapping).
__global__ void prep_w2h(const float* __restrict__ W2) {
    int i = blockIdx.x * 256 + threadIdx.x;
    if (i >= 32 * 2 * 32 * 4) return;
    int q    = i & 3;
    int lane = (i >> 2) & 31;
    int pa   = (i >> 7) & 1;
    int gka  = i >> 8;
    int r = gka * 16 + (lane & 3) * 2 + (q & 1) * 8;
    int n = pa * 16 + ((q >> 1) << 3) + (lane >> 2);
    float v0 = __ldg(&W2[r * DDn + n]);
    float v1 = __ldg(&W2[(r + 1) * DDn + n]);
    ((u32*)g_W2h)[i] = pack2(v0, v1);
}

// ---------------- fused Euler step ----------------
__global__ void __launch_bounds__(NTH, 4)
step_kernel(const float* __restrict__ src, float* __restrict__ dst,
            const int* __restrict__ index,
            const uint4* __restrict__ W1h, const uint4* __restrict__ W2h,
            const float* __restrict__ b1, const float* __restrict__ b2)
{
    extern __shared__ u32 smu[];
    u32*   Zu   = smu;                   // fp16 A-frags: [mb(2)][ka16(10)][lane(32)][slot(4)]
    u32*   b1hs = smu + SM_B1;           // b1 as half2[256]
    float* b2s  = (float*)(smu + SM_B2);
    int*   bas  = (int*)(smu + SM_BAS);
    float* red  = (float*)smu;           // reduction scratch reuses Zf after GEMMs

    const int tid  = threadIdx.x;
    const int lane = tid & 31;
    const int wn   = tid >> 5;   // warp = N slice: 64-col slice within each 256-chunk (0..3)
    const int m0   = blockIdx.x * TMm;
    const int rows_valid = min(TMm, M_TOT - m0);

    // gather bases (element offsets; one per thread: 32 rows x 4 neighbors)
    {
        int r = tid >> 2, k = tid & 3;
        int base = 0;
        if (r < rows_valid) {
            int m = m0 + r, b = m / Nn, n = m - b * Nn;
            base = (b * Nn + __ldg(&index[n * 4 + k])) * Dn;
        }
        bas[tid] = base;
    }
    // b1 -> half2 pairs in smem (128 threads x 4 floats = 512)
    {
        float4 v = __ldg(((const float4*)b1) + tid);
        b1hs[tid * 2]     = pack2(v.x, v.y);
        b1hs[tid * 2 + 1] = pack2(v.z, v.w);
    }
    if (tid < 8) ((float4*)b2s)[tid] = __ldg(((const float4*)b2) + tid);
    __syncthreads();

    // ---- gather Z -> fp16 A-fragment layout (R11-proven: d4-major, MLP=10) ----
    {
        float4 gv[10];
        int rka[10], d4a[10];
        #pragma unroll
        for (int j = 0; j < 10; ++j) {
            int t  = j * NTH + tid;          // 0..1279
            int rk = t / 10;
            int d4 = t - rk * 10;
            rka[j] = rk; d4a[j] = d4;
            gv[j] = __ldg((const float4*)(src + bas[rk] + d4 * 4));
        }
        #pragma unroll
        for (int j = 0; j < 10; ++j) {
            int rk = rka[j], d4 = d4a[j];
            int r  = rk >> 2, kn = rk & 3;
            int K  = kn * 40 + d4 * 4;
            int ka = K >> 4, kk = K & 15;
            int mb = r >> 4, rr = r & 15;
            int lane0 = ((rr & 7) << 2) + ((kk & 7) >> 1);
            int slot  = (rr >> 3) + ((kk >> 3) << 1);
            int base  = ((mb * KA16 + ka) * 32 + lane0) * 4 + slot;
            Zu[base]     = pack2(gv[j].x, gv[j].y);
            Zu[base + 4] = pack2(gv[j].z, gv[j].w);
        }
    }
    __syncthreads();

    float d2[2][4][4];
    #pragma unroll
    for (int m = 0; m < 2; ++m)
        #pragma unroll
        for (int a = 0; a < 4; ++a)
            #pragma unroll
            for (int q = 0; q < 4; ++q) d2[m][a][q] = 0.f;

    const uint4* Za = (const uint4*)Zu;
    const int ccol = 2 * (lane & 3);

    // ---- 2 H-chunks of 256 cols; each warp owns a 32-row x 64-col tile (4 npairs).
    //      GEMM1 accumulates in fp16 (halves d1 regs; D frag == gelu's half2 pair). ----
    #pragma unroll 1
    for (int nc = 0; nc < 2; ++nc) {
        const int npA = nc * 16 + wn * 4;    // warp's 4 npairs
        u32 d1h[2][8][2];                    // [mb][natom][row_lo/row_hi] f16x2 accums
        #pragma unroll
        for (int m = 0; m < 2; ++m)
            #pragma unroll
            for (int a = 0; a < 8; ++a)
                { d1h[m][a][0] = 0u; d1h[m][a][1] = 0u; }

        #pragma unroll
        for (int ka = 0; ka < KA16; ++ka) {
            uint4 av0 = Za[(0 * KA16 + ka) * 32 + lane];
            uint4 av1 = Za[(1 * KA16 + ka) * 32 + lane];
            u32 a0[4] = {av0.x, av0.y, av0.z, av0.w};
            u32 a1[4] = {av1.x, av1.y, av1.z, av1.w};
            #pragma unroll
            for (int p = 0; p < 4; ++p) {
                uint4 bw = __ldg(W1h + (ka * 32 + npA + p) * 32 + lane);
                MMAH2(d1h[0][2*p],   a0, bw.x, bw.y);
                MMAH2(d1h[1][2*p],   a1, bw.x, bw.y);
                MMAH2(d1h[0][2*p+1], a0, bw.z, bw.w);
                MMAH2(d1h[1][2*p+1], a1, bw.z, bw.w);
            }
        }

        // ---- bias + gelu fully in half2, feed GEMM2 from registers ----
        const int colbase = nc * 256 + wn * 64;
        #pragma unroll
        for (int pg = 0; pg < 4; ++pg) {
            int cE = colbase + pg * 16 + ccol;     // even atom cols (2c,2c+1)
            int cO = cE + 8;                       // odd atom cols
            u32 bE = b1hs[cE >> 1];
            u32 bO = b1hs[cO >> 1];
            __half2 bEh = *(__half2*)&bE, bOh = *(__half2*)&bO;
            u32 A2[2][4];
            #pragma unroll
            for (int m = 0; m < 2; ++m) {
                __half2 e0 = __hadd2(*(__half2*)&d1h[m][2*pg][0],   bEh);
                __half2 e1 = __hadd2(*(__half2*)&d1h[m][2*pg][1],   bEh);
                __half2 o0 = __hadd2(*(__half2*)&d1h[m][2*pg+1][0], bOh);
                __half2 o1 = __hadd2(*(__half2*)&d1h[m][2*pg+1][1], bOh);
                A2[m][0] = gelu2h(*(u32*)&e0);
                A2[m][1] = gelu2h(*(u32*)&e1);
                A2[m][2] = gelu2h(*(u32*)&o0);
                A2[m][3] = gelu2h(*(u32*)&o1);
            }
            int gka = nc * 16 + wn * 4 + pg;       // H 16-row block (0..31)
            #pragma unroll
            for (int pa = 0; pa < 2; ++pa) {
                uint4 w = __ldg(W2h + (gka * 2 + pa) * 32 + lane);
                MMAH(d2[0][2*pa],   A2[0], w.x, w.y);
                MMAH(d2[1][2*pa],   A2[1], w.x, w.y);
                MMAH(d2[0][2*pa+1], A2[0], w.z, w.w);
                MMAH(d2[1][2*pa+1], A2[1], w.z, w.w);
            }
        }
    }

    __syncthreads();   // all Zf reads done before red overwrites it

    // ---- cross-wn reduction: wn=1..3 store partial d2, wn=0 adds ----
    if (wn >= 1) {
        float* rp = red + ((wn - 1) * 32 + lane) * 36;
        #pragma unroll
        for (int m = 0; m < 2; ++m)
            #pragma unroll
            for (int a = 0; a < 4; ++a)
                *(float4*)&rp[(m * 4 + a) * 4] =
                    make_float4(d2[m][a][0], d2[m][a][1], d2[m][a][2], d2[m][a][3]);
    }
    __syncthreads();

    if (wn == 0) {
        #pragma unroll
        for (int s = 0; s < 3; ++s) {
            const float* rp = red + (s * 32 + lane) * 36;
            #pragma unroll
            for (int m = 0; m < 2; ++m)
                #pragma unroll
                for (int a = 0; a < 4; ++a) {
                    float4 v = *(const float4*)&rp[(m * 4 + a) * 4];
                    d2[m][a][0] += v.x; d2[m][a][1] += v.y;
                    d2[m][a][2] += v.z; d2[m][a][3] += v.w;
                }
        }
        // epilogue: dst[row][c..c+1] = x + 0.1*(d2 + b2)
        #pragma unroll
        for (int m = 0; m < 2; ++m)
            #pragma unroll
            for (int rr = 0; rr < 2; ++rr) {
                int row = m * 16 + rr * 8 + (lane >> 2);
                if (row < rows_valid) {
                    size_t rb = (size_t)(m0 + row) * Dn;
                    #pragma unroll
                    for (int a = 0; a < 4; ++a) {
                        int c = a * 8 + ccol;
                        float2 xv = __ldg((const float2*)(src + rb + c));
                        float2 ov;
                        ov.x = xv.x + 0.1f * (d2[m][a][rr*2]     + b2s[c]);
                        ov.y = xv.y + 0.1f * (d2[m][a][rr*2 + 1] + b2s[c+1]);
                        *(float2*)(dst + rb + c) = ov;
                    }
                }
            }
    } else if (wn == 1) {
        // static dims 32..39 (unchanged by Euler step)
        int row = lane;
        if (row < rows_valid) {
            size_t rb = (size_t)(m0 + row) * Dn;
            float4 s0 = __ldg((const float4*)(src + rb + 32));
            float4 s1 = __ldg((const float4*)(src + rb + 36));
            *(float4*)(dst + rb + 32) = s0;
            *(float4*)(dst + rb + 36) = s1;
        }
    }
}

extern "C" void kernel_launch(void* const* d_in, const int* in_sizes, int n_in,
                              void* d_out, int out_size)
{
    const float* x     = (const float*)d_in[0];
    const int*   index = (const int*)  d_in[1];
    const float* W1    = (const float*)d_in[2];
    const float* b1    = (const float*)d_in[3];
    const float* W2    = (const float*)d_in[4];
    const float* b2    = (const float*)d_in[5];
    float* out = (float*)d_out;

    float* buf = nullptr;
    uint4 *w1h = nullptr, *w2h = nullptr;
    cudaGetSymbolAddress((void**)&buf, g_xbuf);
    cudaGetSymbolAddress((void**)&w1h, g_W1h);
    cudaGetSymbolAddress((void**)&w2h, g_W2h);

    cudaFuncSetAttribute(step_kernel, cudaFuncAttributeMaxDynamicSharedMemorySize, SMEM_BYTES);

    prep_w1h<<<(KA16*32*32*4 + 255)/256, 256>>>(W1);
    prep_w2h<<<(32*2*32*4 + 255)/256, 256>>>(W2);

    dim3 grid(NBLK), block(NTH);
    step_kernel<<<grid, block, SMEM_BYTES>>>(x,   buf, index, w1h, w2h, b1, b2);
    step_kernel<<<grid, block, SMEM_BYTES>>>(buf, out, index, w1h, w2h, b1, b2);
    step_kernel<<<grid, block, SMEM_BYTES>>>(out, buf, index, w1h, w2h, b1, b2);
    step_kernel<<<grid, block, SMEM_BYTES>>>(buf, out, index, w1h, w2h, b1, b2);
}

// round 14
// speedup vs baseline: 1.2664x; 1.0644x over previous
#include <cuda_runtime.h>
#include <cuda_fp16.h>
#include <cstdint>

typedef unsigned int u32;

// ---------------- problem constants ----------------
#define Bn 8
#define Nn 40962
#define Dn 40
#define Hn 512
#define DDn 32
#define KTOT 160               // 4 neighbors * 40
#define M_TOT (Bn*Nn)          // 327696
#define TMm 32                 // rows per CTA (4 CTAs/SM)
#define NTH 128
#define NBLK ((M_TOT + TMm - 1)/TMm)   // 10241
#define KA16 10                // GEMM1 k-atoms of 16 (160/16)

// ---------------- smem layout (u32 indices) ----------------
// region A: max(Zf 2560 u32, red 1536 u32) = 2560... keep 3456 slack
#define SM_Z    0
#define SM_B1   3456           // b1 as half2[256]
#define SM_B2   (SM_B1 + 512)
#define SM_BAS  (SM_B2 + 32)
#define SM_U32S (SM_BAS + 128)         // 4128
#define SMEM_BYTES (SM_U32S*4)         // 16512

// ---------------- helpers ----------------
__device__ __forceinline__ u32 pack2(float a, float b) {
    __half2 h = __floats2half2_rn(a, b);
    return *(u32*)&h;
}
// full-half2 gelu: u = x*(c1 + c2*x^2); h = x*(0.5*tanh(u)+0.5)
__device__ __forceinline__ u32 gelu2h(u32 xu) {
    __half2 xh = *(__half2*)&xu;
    const __half2 c1h = __float2half2_rn(0.7978845608028654f);
    const __half2 c2h = __float2half2_rn(0.0356774081f);
    const __half2 c05 = __float2half2_rn(0.5f);
    __half2 x2 = __hmul2(xh, xh);
    __half2 u  = __hmul2(xh, __hfma2(c2h, x2, c1h));
    u32 uu = *(u32*)&u;
    u32 tu; asm("tanh.approx.f16x2 %0, %1;" : "=r"(tu) : "r"(uu));
    __half2 t = *(__half2*)&tu;
    __half2 h = __hmul2(xh, __hfma2(t, c05, c05));
    return *(u32*)&h;
}

// m16n8k16 fp16 HMMA, f16 accum: D = 2 u32 (4 halves)
#define MMAH2(D, A, b0, b1) \
    asm("mma.sync.aligned.m16n8k16.row.col.f16.f16.f16.f16 " \
        "{%0,%1}, {%2,%3,%4,%5}, {%6,%7}, {%0,%1};" \
        : "+r"((D)[0]), "+r"((D)[1]) \
        : "r"((A)[0]), "r"((A)[1]), "r"((A)[2]), "r"((A)[3]), "r"(b0), "r"(b1))

// ---------------- global scratch ----------------
// W1 fp16 B-fragments: [ka16(10)][npair(32)][lane(32)] x uint4
__device__ uint4 g_W1h[KA16 * 32 * 32];
// W2 fp16 B-fragments: [gka16(32)][pa(2)][lane(32)] x uint4
__device__ uint4 g_W2h[32 * 2 * 32];
__device__ float g_xbuf[(size_t)M_TOT * Dn];

// prep: W1 -> fp16 B-frag order.
__global__ void prep_w1h(const float* __restrict__ W1) {
    int i = blockIdx.x * 256 + threadIdx.x;
    if (i >= KA16 * 32 * 32 * 4) return;
    int q    = i & 3;
    int lane = (i >> 2) & 31;
    int np   = (i >> 7) & 31;
    int ka   = i >> 12;
    int k = ka * 16 + (lane & 3) * 2 + (q & 1) * 8;
    int n = np * 16 + ((q >> 1) << 3) + (lane >> 2);
    float v0 = __ldg(&W1[(size_t)k * Hn + n]);
    float v1 = __ldg(&W1[(size_t)(k + 1) * Hn + n]);
    ((u32*)g_W1h)[i] = pack2(v0, v1);
}

// prep: W2 -> fp16 B-frag order (identity k mapping).
__global__ void prep_w2h(const float* __restrict__ W2) {
    int i = blockIdx.x * 256 + threadIdx.x;
    if (i >= 32 * 2 * 32 * 4) return;
    int q    = i & 3;
    int lane = (i >> 2) & 31;
    int pa   = (i >> 7) & 1;
    int gka  = i >> 8;
    int r = gka * 16 + (lane & 3) * 2 + (q & 1) * 8;
    int n = pa * 16 + ((q >> 1) << 3) + (lane >> 2);
    float v0 = __ldg(&W2[r * DDn + n]);
    float v1 = __ldg(&W2[(r + 1) * DDn + n]);
    ((u32*)g_W2h)[i] = pack2(v0, v1);
}

// ---------------- fused Euler step ----------------
__global__ void __launch_bounds__(NTH, 4)
step_kernel(const float* __restrict__ src, float* __restrict__ dst,
            const int* __restrict__ index,
            const uint4* __restrict__ W1h, const uint4* __restrict__ W2h,
            const float* __restrict__ b1, const float* __restrict__ b2)
{
    extern __shared__ u32 smu[];
    u32*   Zu   = smu;                   // fp16 A-frags: [mb(2)][ka16(10)][lane(32)][slot(4)]
    u32*   b1hs = smu + SM_B1;           // b1 as half2[256]
    float* b2s  = (float*)(smu + SM_B2);
    int*   bas  = (int*)(smu + SM_BAS);
    u32*   redu = smu;                   // reduction scratch reuses Zf after GEMMs

    const int tid  = threadIdx.x;
    const int lane = tid & 31;
    const int wn   = tid >> 5;   // warp = N slice: 128-col slice of H (0..3)
    const int m0   = blockIdx.x * TMm;
    const int rows_valid = min(TMm, M_TOT - m0);

    // gather bases (element offsets; one per thread: 32 rows x 4 neighbors)
    {
        int r = tid >> 2, k = tid & 3;
        int base = 0;
        if (r < rows_valid) {
            int m = m0 + r, b = m / Nn, n = m - b * Nn;
            base = (b * Nn + __ldg(&index[n * 4 + k])) * Dn;
        }
        bas[tid] = base;
    }
    // b1 -> half2 pairs in smem
    {
        float4 v = __ldg(((const float4*)b1) + tid);
        b1hs[tid * 2]     = pack2(v.x, v.y);
        b1hs[tid * 2 + 1] = pack2(v.z, v.w);
    }
    if (tid < 8) ((float4*)b2s)[tid] = __ldg(((const float4*)b2) + tid);
    __syncthreads();

    // ---- gather Z -> fp16 A-fragment layout (d4-major, MLP=10) ----
    {
        float4 gv[10];
        int rka[10], d4a[10];
        #pragma unroll
        for (int j = 0; j < 10; ++j) {
            int t  = j * NTH + tid;          // 0..1279
            int rk = t / 10;
            int d4 = t - rk * 10;
            rka[j] = rk; d4a[j] = d4;
            gv[j] = __ldg((const float4*)(src + bas[rk] + d4 * 4));
        }
        #pragma unroll
        for (int j = 0; j < 10; ++j) {
            int rk = rka[j], d4 = d4a[j];
            int r  = rk >> 2, kn = rk & 3;
            int K  = kn * 40 + d4 * 4;
            int ka = K >> 4, kk = K & 15;
            int mb = r >> 4, rr = r & 15;
            int lane0 = ((rr & 7) << 2) + ((kk & 7) >> 1);
            int slot  = (rr >> 3) + ((kk >> 3) << 1);
            int base  = ((mb * KA16 + ka) * 32 + lane0) * 4 + slot;
            Zu[base]     = pack2(gv[j].x, gv[j].y);
            Zu[base + 4] = pack2(gv[j].z, gv[j].w);
        }
    }
    __syncthreads();

    const uint4* Za = (const uint4*)Zu;
    const int ccol = 2 * (lane & 3);
    const int npA  = wn * 8;      // warp's 8 npairs (128 H-cols)

    // ---- single-pass GEMM1: each warp 32 rows x 128 cols, f16 accum ----
    u32 d1h[2][16][2];            // [mb][natom][row_lo/row_hi] f16x2 accums
    #pragma unroll
    for (int m = 0; m < 2; ++m)
        #pragma unroll
        for (int a = 0; a < 16; ++a)
            { d1h[m][a][0] = 0u; d1h[m][a][1] = 0u; }

    #pragma unroll
    for (int ka = 0; ka < KA16; ++ka) {
        uint4 av0 = Za[(0 * KA16 + ka) * 32 + lane];
        uint4 av1 = Za[(1 * KA16 + ka) * 32 + lane];
        u32 a0[4] = {av0.x, av0.y, av0.z, av0.w};
        u32 a1[4] = {av1.x, av1.y, av1.z, av1.w};
        #pragma unroll
        for (int p = 0; p < 8; ++p) {
            uint4 bw = __ldg(W1h + (ka * 32 + npA + p) * 32 + lane);
            MMAH2(d1h[0][2*p],   a0, bw.x, bw.y);
            MMAH2(d1h[1][2*p],   a1, bw.x, bw.y);
            MMAH2(d1h[0][2*p+1], a0, bw.z, bw.w);
            MMAH2(d1h[1][2*p+1], a1, bw.z, bw.w);
        }
    }

    // ---- bias + gelu (half2) + GEMM2 partial (f16 accum) ----
    u32 d2h[2][4][2];             // [mb][natom][row_lo/row_hi] f16x2 accums
    #pragma unroll
    for (int m = 0; m < 2; ++m)
        #pragma unroll
        for (int a = 0; a < 4; ++a)
            { d2h[m][a][0] = 0u; d2h[m][a][1] = 0u; }

    #pragma unroll
    for (int pg = 0; pg < 8; ++pg) {
        int cE = wn * 128 + pg * 16 + ccol;    // even atom cols (2c,2c+1)
        int cO = cE + 8;                       // odd atom cols
        u32 bE = b1hs[cE >> 1];
        u32 bO = b1hs[cO >> 1];
        __half2 bEh = *(__half2*)&bE, bOh = *(__half2*)&bO;
        u32 A2[2][4];
        #pragma unroll
        for (int m = 0; m < 2; ++m) {
            __half2 e0 = __hadd2(*(__half2*)&d1h[m][2*pg][0],   bEh);
            __half2 e1 = __hadd2(*(__half2*)&d1h[m][2*pg][1],   bEh);
            __half2 o0 = __hadd2(*(__half2*)&d1h[m][2*pg+1][0], bOh);
            __half2 o1 = __hadd2(*(__half2*)&d1h[m][2*pg+1][1], bOh);
            A2[m][0] = gelu2h(*(u32*)&e0);
            A2[m][1] = gelu2h(*(u32*)&e1);
            A2[m][2] = gelu2h(*(u32*)&o0);
            A2[m][3] = gelu2h(*(u32*)&o1);
        }
        int gka = npA + pg;                    // H 16-row block (0..31)
        #pragma unroll
        for (int pa = 0; pa < 2; ++pa) {
            uint4 w = __ldg(W2h + (gka * 2 + pa) * 32 + lane);
            MMAH2(d2h[0][2*pa],   A2[0], w.x, w.y);
            MMAH2(d2h[1][2*pa],   A2[1], w.x, w.y);
            MMAH2(d2h[0][2*pa+1], A2[0], w.z, w.w);
            MMAH2(d2h[1][2*pa+1], A2[1], w.z, w.w);
        }
    }

    __syncthreads();   // all Zf reads done before redu overwrites it

    // ---- cross-wn reduction: wn=1..3 store f16 partials, wn=0 sums in f32 ----
    if (wn >= 1) {
        u32* rp = redu + ((wn - 1) * 32 + lane) * 16;
        #pragma unroll
        for (int m = 0; m < 2; ++m)
            #pragma unroll
            for (int a = 0; a < 4; ++a) {
                rp[(m * 4 + a) * 2]     = d2h[m][a][0];
                rp[(m * 4 + a) * 2 + 1] = d2h[m][a][1];
            }
    }
    __syncthreads();

    if (wn == 0) {
        float d2[2][4][4];
        #pragma unroll
        for (int m = 0; m < 2; ++m)
            #pragma unroll
            for (int a = 0; a < 4; ++a) {
                float2 lo = __half22float2(*(__half2*)&d2h[m][a][0]);
                float2 hi = __half22float2(*(__half2*)&d2h[m][a][1]);
                d2[m][a][0] = lo.x; d2[m][a][1] = lo.y;
                d2[m][a][2] = hi.x; d2[m][a][3] = hi.y;
            }
        #pragma unroll
        for (int s = 0; s < 3; ++s) {
            const u32* rp = redu + (s * 32 + lane) * 16;
            #pragma unroll
            for (int m = 0; m < 2; ++m)
                #pragma unroll
                for (int a = 0; a < 4; ++a) {
                    float2 lo = __half22float2(*(__half2*)&rp[(m * 4 + a) * 2]);
                    float2 hi = __half22float2(*(__half2*)&rp[(m * 4 + a) * 2 + 1]);
                    d2[m][a][0] += lo.x; d2[m][a][1] += lo.y;
                    d2[m][a][2] += hi.x; d2[m][a][3] += hi.y;
                }
        }
        // epilogue: dst[row][c..c+1] = x + 0.1*(d2 + b2)
        #pragma unroll
        for (int m = 0; m < 2; ++m)
            #pragma unroll
            for (int rr = 0; rr < 2; ++rr) {
                int row = m * 16 + rr * 8 + (lane >> 2);
                if (row < rows_valid) {
                    size_t rb = (size_t)(m0 + row) * Dn;
                    #pragma unroll
                    for (int a = 0; a < 4; ++a) {
                        int c = a * 8 + ccol;
                        float2 xv = __ldg((const float2*)(src + rb + c));
                        float2 ov;
                        ov.x = xv.x + 0.1f * (d2[m][a][rr*2]     + b2s[c]);
                        ov.y = xv.y + 0.1f * (d2[m][a][rr*2 + 1] + b2s[c+1]);
                        *(float2*)(dst + rb + c) = ov;
                    }
                }
            }
    } else if (wn == 1) {
        // static dims 32..39 (unchanged by Euler step)
        int row = lane;
        if (row < rows_valid) {
            size_t rb = (size_t)(m0 + row) * Dn;
            float4 s0 = __ldg((const float4*)(src + rb + 32));
            float4 s1 = __ldg((const float4*)(src + rb + 36));
            *(float4*)(dst + rb + 32) = s0;
            *(float4*)(dst + rb + 36) = s1;
        }
    }
}

extern "C" void kernel_launch(void* const* d_in, const int* in_sizes, int n_in,
                              void* d_out, int out_size)
{
    const float* x     = (const float*)d_in[0];
    const int*   index = (const int*)  d_in[1];
    const float* W1    = (const float*)d_in[2];
    const float* b1    = (const float*)d_in[3];
    const float* W2    = (const float*)d_in[4];
    const float* b2    = (const float*)d_in[5];
    float* out = (float*)d_out;

    float* buf = nullptr;
    uint4 *w1h = nullptr, *w2h = nullptr;
    cudaGetSymbolAddress((void**)&buf, g_xbuf);
    cudaGetSymbolAddress((void**)&w1h, g_W1h);
    cudaGetSymbolAddress((void**)&w2h, g_W2h);

    cudaFuncSetAttribute(step_kernel, cudaFuncAttributeMaxDynamicSharedMemorySize, SMEM_BYTES);

    prep_w1h<<<(KA16*32*32*4 + 255)/256, 256>>>(W1);
    prep_w2h<<<(32*2*32*4 + 255)/256, 256>>>(W2);

    dim3 grid(NBLK), block(NTH);
    step_kernel<<<grid, block, SMEM_BYTES>>>(x,   buf, index, w1h, w2h, b1, b2);
    step_kernel<<<grid, block, SMEM_BYTES>>>(buf, out, index, w1h, w2h, b1, b2);
    step_kernel<<<grid, block, SMEM_BYTES>>>(out, buf, index, w1h, w2h, b1, b2);
    step_kernel<<<grid, block, SMEM_BYTES>>>(buf, out, index, w1h, w2h, b1, b2);
}